// round 1
// baseline (speedup 1.0000x reference)
#include <cuda_runtime.h>
#include <math.h>

// Problem constants
#define MTOT 16384      // B*S tokens
#define KDIM 4096       // D
#define EEXP 64         // experts
#define NCMB 128        // combined N = 2*E (route | noise)
#define TOPK 8

// Output layout (all float32, tuple order flattened):
//   [0, 131072)        weighted    [B,S,K]
//   [131072, 262144)   selected    [B,S,K]  (indices as float)
//   [262144, 1310720)  probs       [B,S,E]
#define WOFF 0
#define IOFF (MTOT * TOPK)
#define POFF (2 * MTOT * TOPK)

// GEMM tiling
#define BM 128
#define BN 128
#define BK 8

// Scratch for combined logits [MTOT, NCMB] (8 MB, static device array per rules)
__device__ float g_logits[MTOT * NCMB];

// ---------------------------------------------------------------------------
// GEMM: g_logits[m, 0:64]  = x[m,:] @ W_route
//       g_logits[m,64:128] = x[m,:] @ W_noise
// 128x128 CTA tile, K-loop of 8, double-buffered smem, 8x8 per thread.
// ---------------------------------------------------------------------------
__global__ __launch_bounds__(256, 1)
void gemm_kernel(const float* __restrict__ X,
                 const float* __restrict__ Wr,
                 const float* __restrict__ Wn)
{
    __shared__ float As[2][BK][BM + 4];   // transposed A tile, padded
    __shared__ float Bs[2][BK][BN];

    const int tid = threadIdx.x;
    const int tx = tid & 15;          // 0..15 -> n sub-tile
    const int ty = tid >> 4;          // 0..15 -> m sub-tile

    // A-tile load mapping: 128 rows x 8 k, one float4 per thread
    const int arow = tid >> 1;        // 0..127
    const int ak4  = (tid & 1) * 4;   // 0 or 4
    const float* aptr = X + (size_t)(blockIdx.x * BM + arow) * KDIM + ak4;

    // B-tile load mapping: 8 k-rows x 128 n, one float4 per thread
    const int bk = tid >> 5;          // 0..7
    const int bn = (tid & 31) * 4;    // 0..124
    const float* bsrc = (bn < EEXP) ? (Wr + bn) : (Wn + (bn - EEXP));

    float acc[8][8];
#pragma unroll
    for (int i = 0; i < 8; i++)
#pragma unroll
        for (int j = 0; j < 8; j++) acc[i][j] = 0.0f;

    // Prologue: load k-tile 0
    float4 ar = *reinterpret_cast<const float4*>(aptr);
    float4 br = *reinterpret_cast<const float4*>(bsrc + (size_t)bk * EEXP);

    As[0][ak4 + 0][arow] = ar.x;
    As[0][ak4 + 1][arow] = ar.y;
    As[0][ak4 + 2][arow] = ar.z;
    As[0][ak4 + 3][arow] = ar.w;
    *reinterpret_cast<float4*>(&Bs[0][bk][bn]) = br;
    __syncthreads();

    const int NT = KDIM / BK;   // 512
    for (int kt = 0; kt < NT; ++kt) {
        const int cur = kt & 1;
        const int nxt = cur ^ 1;

        // Prefetch next tile into registers
        if (kt + 1 < NT) {
            ar = *reinterpret_cast<const float4*>(aptr + (size_t)(kt + 1) * BK);
            br = *reinterpret_cast<const float4*>(bsrc + (size_t)((kt + 1) * BK + bk) * EEXP);
        }

        // Compute current tile
#pragma unroll
        for (int kk = 0; kk < BK; ++kk) {
            float a[8], b[8];
            *reinterpret_cast<float4*>(&a[0]) = *reinterpret_cast<const float4*>(&As[cur][kk][ty * 8 + 0]);
            *reinterpret_cast<float4*>(&a[4]) = *reinterpret_cast<const float4*>(&As[cur][kk][ty * 8 + 4]);
            *reinterpret_cast<float4*>(&b[0]) = *reinterpret_cast<const float4*>(&Bs[cur][kk][tx * 8 + 0]);
            *reinterpret_cast<float4*>(&b[4]) = *reinterpret_cast<const float4*>(&Bs[cur][kk][tx * 8 + 4]);
#pragma unroll
            for (int i = 0; i < 8; i++)
#pragma unroll
                for (int j = 0; j < 8; j++)
                    acc[i][j] = fmaf(a[i], b[j], acc[i][j]);
        }

        // Stage next tile to smem
        if (kt + 1 < NT) {
            As[nxt][ak4 + 0][arow] = ar.x;
            As[nxt][ak4 + 1][arow] = ar.y;
            As[nxt][ak4 + 2][arow] = ar.z;
            As[nxt][ak4 + 3][arow] = ar.w;
            *reinterpret_cast<float4*>(&Bs[nxt][bk][bn]) = br;
        }
        __syncthreads();
    }

    // Write 8x8 result block
    float* orow = g_logits + (size_t)(blockIdx.x * BM + ty * 8) * NCMB + tx * 8;
#pragma unroll
    for (int i = 0; i < 8; i++) {
        float4 v0 = make_float4(acc[i][0], acc[i][1], acc[i][2], acc[i][3]);
        float4 v1 = make_float4(acc[i][4], acc[i][5], acc[i][6], acc[i][7]);
        *reinterpret_cast<float4*>(orow + (size_t)i * NCMB + 0) = v0;
        *reinterpret_cast<float4*>(orow + (size_t)i * NCMB + 4) = v1;
    }
}

// ---------------------------------------------------------------------------
// Router: softplus noise mix -> softmax(E=64) -> top-8 -> outputs
// One warp per token; each lane owns experts (lane, lane+32).
// ---------------------------------------------------------------------------
__device__ __forceinline__ float softplus_f(float z) {
    // jax.nn.softplus = logaddexp(z, 0) = max(z,0) + log1p(exp(-|z|))
    return fmaxf(z, 0.0f) + log1pf(expf(-fabsf(z)));
}

__global__ __launch_bounds__(256, 8)
void router_kernel(const float* __restrict__ noise,
                   const float* __restrict__ b_route,
                   const float* __restrict__ b_noise,
                   float* __restrict__ out)
{
    const int lane = threadIdx.x & 31;
    const int wrp  = threadIdx.x >> 5;
    const int token = blockIdx.x * 8 + wrp;

    const float* row = g_logits + (size_t)token * NCMB;
    const int e0 = lane, e1 = lane + 32;

    float lr0 = row[e0] + b_route[e0];
    float lr1 = row[e1] + b_route[e1];
    float ln0 = row[EEXP + e0] + b_noise[e0];
    float ln1 = row[EEXP + e1] + b_noise[e1];

    const float* nz = noise + (size_t)token * EEXP;
    float l0 = lr0 + nz[e0] * softplus_f(ln0);
    float l1 = lr1 + nz[e1] * softplus_f(ln1);

    // softmax over 64
    float mx = fmaxf(l0, l1);
#pragma unroll
    for (int o = 16; o > 0; o >>= 1) mx = fmaxf(mx, __shfl_xor_sync(0xFFFFFFFFu, mx, o));
    float p0 = expf(l0 - mx);
    float p1 = expf(l1 - mx);
    float sum = p0 + p1;
#pragma unroll
    for (int o = 16; o > 0; o >>= 1) sum += __shfl_xor_sync(0xFFFFFFFFu, sum, o);
    p0 /= sum;
    p1 /= sum;

    out[POFF + (size_t)token * EEXP + e0] = p0;
    out[POFF + (size_t)token * EEXP + e1] = p1;

    // top-8 via iterative warp argmax (lower-index tiebreak, matches lax.top_k)
    float v0 = p0, v1 = p1;
    float myv = 0.0f;
    int   mye = 0;
    float tsum = 0.0f;

#pragma unroll
    for (int i = 0; i < TOPK; i++) {
        float cv; int ce;
        if (v1 > v0) { cv = v1; ce = e1; } else { cv = v0; ce = e0; }
#pragma unroll
        for (int o = 16; o > 0; o >>= 1) {
            float ov = __shfl_xor_sync(0xFFFFFFFFu, cv, o);
            int   oe = __shfl_xor_sync(0xFFFFFFFFu, ce, o);
            if (ov > cv || (ov == cv && oe < ce)) { cv = ov; ce = oe; }
        }
        tsum += cv;
        if (lane == i) { myv = cv; mye = ce; }
        if (ce == e0) v0 = -1e30f;
        else if (ce == e1) v1 = -1e30f;
    }

    if (lane < TOPK) {
        out[WOFF + (size_t)token * TOPK + lane] = myv / tsum;
        out[IOFF + (size_t)token * TOPK + lane] = (float)mye;
    }
}

// ---------------------------------------------------------------------------
extern "C" void kernel_launch(void* const* d_in, const int* in_sizes, int n_in,
                              void* d_out, int out_size)
{
    const float* x     = (const float*)d_in[0];   // [B,S,D]
    const float* noise = (const float*)d_in[1];   // [B,S,E]
    const float* Wr    = (const float*)d_in[2];   // [D,E]
    const float* br    = (const float*)d_in[3];   // [E]
    const float* Wn    = (const float*)d_in[4];   // [D,E]
    const float* bn    = (const float*)d_in[5];   // [E]
    float* out = (float*)d_out;

    gemm_kernel<<<MTOT / BM, 256>>>(x, Wr, Wn);
    router_kernel<<<MTOT / 8, 256>>>(noise, br, bn, out);
}